// round 13
// baseline (speedup 1.0000x reference)
#include <cuda_runtime.h>

#define ED 2048
#define EDV 512          // float4s per row
#define NH 16
#define HD 128
#define LCACHE 8192
#define L1 8193

// scratch (no allocs allowed)
__device__ float g_q[ED];      // q = x@Wq + bq
__device__ float g_hsum[NH];   // sum of exp(score) over rows [0,8192)
__device__ float g_vals[ED];   // sum of exp(score)*v (rows [0,8192))
// monotonic counters (never reset -> replay-safe via epoch arithmetic)
__device__ unsigned g_enter;   // +256 per launch (epoch source)
__device__ unsigned g_qcnt;    // +65 per launch (64 Wq blocks + init block)
__device__ unsigned g_scnt;    // +256 per launch (stream done)

// ---------------------------------------------------------------------------
// ONE persistent kernel: 256 blocks x 512 threads, occ 2 -> all resident
// (256 < 2*148), so in-kernel spin barriers are deadlock-free.
//
// Phase 1 (uniform 256KB/block):
//   b in [0,64):    q cols   [32b, 32b+32)        -> g_q      (arrive g_qcnt)
//   b in [64,128):  k_i cols                       -> k_tail
//   b in [128,192): v_i cols                       -> v_tail
//   b == 192:       zero g_hsum/g_vals, out_i = bo (arrive g_qcnt)
// Barrier 1 (g_qcnt == 65*(epoch+1)): q + accumulators ready.
// Phase 2: ALL 256 blocks stream KV rows (proj blocks 30 rows, spares 38 —
//   equalizes total per-block traffic): read k row -> score -> copy out_k;
//   read v row -> acc exp(s)*v -> copy out_v.  Warp w == head w.
//   Unnormalized softmax accumulators via atomics.
// Barrier 2 (g_scnt == 256*(epoch+1)).
// Phase 3: every block redundantly computes tail e_h = exp(q_h.k_tail_h*sc)
//   and sinv_h = 1/(hsum_h + e_h) (race-free), then oproj partial GEMV:
//   block = (row-slice of 256) x (64-col group) over Wo with
//   x[i] = (g_vals[i] + e_h*v_tail[i])*sinv_h; atomicAdd into out_i.
// ---------------------------------------------------------------------------
__global__ void __launch_bounds__(512, 2)
mega_kernel(const float* __restrict__ kc, const float* __restrict__ vc,
            const float* __restrict__ x,
            const float* __restrict__ Wq, const float* __restrict__ bq,
            const float* __restrict__ Wk, const float* __restrict__ bk,
            const float* __restrict__ Wv, const float* __restrict__ bv,
            const float* __restrict__ Wo, const float* __restrict__ bo,
            float* __restrict__ out_k, float* __restrict__ out_v,
            float* __restrict__ k_tail, float* __restrict__ v_tail,
            float* __restrict__ out_i,
            float scale) {
    __shared__ float  sx[ED];
    __shared__ float  red[16][32];
    __shared__ float4 red4[32][16];
    __shared__ float  sxs[256];
    __shared__ float  ssinv[NH];
    __shared__ float  se[NH];
    __shared__ unsigned s_epoch;

    int t = threadIdx.x;
    int b = blockIdx.x;
    if (t == 0) s_epoch = atomicAdd(&g_enter, 1u) >> 8;
    __syncthreads();
    unsigned epoch = s_epoch;

    // ------------------------- phase 1 -------------------------
    if (b < 192) {
        int m  = b >> 6;                 // 0=q, 1=k, 2=v
        int jb = (b & 63) * 32;
        const float* W  = (m == 0) ? Wq : (m == 1) ? Wk : Wv;
        const float* bb = (m == 0) ? bq : (m == 1) ? bk : bv;

        for (int i = t; i < ED; i += 512) sx[i] = x[i];
        __syncthreads();

        int j = jb + (t & 31);
        int isub = t >> 5;
        float a0 = 0.f, a1 = 0.f, a2 = 0.f, a3 = 0.f;
        for (int i = isub; i < ED; i += 64) {
            a0 += sx[i]      * W[(size_t)i * ED + j];
            a1 += sx[i + 16] * W[(size_t)(i + 16) * ED + j];
            a2 += sx[i + 32] * W[(size_t)(i + 32) * ED + j];
            a3 += sx[i + 48] * W[(size_t)(i + 48) * ED + j];
        }
        red[isub][t & 31] = (a0 + a1) + (a2 + a3);
        __syncthreads();
        if (t < 32) {
            float r = bb[jb + t];
            #pragma unroll
            for (int s = 0; s < 16; ++s) r += red[s][t];
            float* dst = (m == 0) ? g_q : (m == 1) ? k_tail : v_tail;
            dst[jb + t] = r;
        }
        if (m == 0) {
            __threadfence();
            __syncthreads();
            if (t == 0) atomicAdd(&g_qcnt, 1u);
        }
    } else if (b == 192) {
        if (t < NH) g_hsum[t] = 0.f;
        for (int i = t; i < ED; i += 512) { g_vals[i] = 0.f; out_i[i] = bo[i]; }
        __threadfence();
        __syncthreads();
        if (t == 0) atomicAdd(&g_qcnt, 1u);
    }

    // ---------------- barrier 1: q + accumulators ready ----------------
    if (t == 0) {
        unsigned target = (epoch + 1u) * 65u;
        while (*(volatile unsigned*)&g_qcnt < target) __nanosleep(32);
    }
    __syncthreads();
    __threadfence();

    // ------------------------- phase 2: stream -------------------------
    {
        int lane = t & 31;
        int h = t >> 5;
        int start, nrows;
        if (b < 192) { start = b * 30;                nrows = 30; }
        else         { start = 5760 + (b - 192) * 38; nrows = 38; }

        float4 q = ((const float4*)g_q)[t];
        const float4* ks = (const float4*)(kc + (size_t)start * ED);
        const float4* vs = (const float4*)(vc + (size_t)start * ED);
        float4* kd = (float4*)(out_k + (size_t)start * ED);
        float4* vd = (float4*)(out_v + (size_t)start * ED);

        float lsum = 0.f;
        float cx = 0.f, cy = 0.f, cz = 0.f, cw = 0.f;
        int r0 = 0;
        for (; r0 + 4 <= nrows; r0 += 4) {
            float4 a[4], bb4[4];
            #pragma unroll
            for (int u = 0; u < 4; ++u) a[u]   = __ldcs(&ks[(r0 + u) * EDV + t]);
            #pragma unroll
            for (int u = 0; u < 4; ++u) bb4[u] = __ldcs(&vs[(r0 + u) * EDV + t]);
            #pragma unroll
            for (int u = 0; u < 4; ++u) __stcs(&kd[(r0 + u) * EDV + t], a[u]);
            float d[4];
            #pragma unroll
            for (int u = 0; u < 4; ++u)
                d[u] = a[u].x * q.x + a[u].y * q.y + a[u].z * q.z + a[u].w * q.w;
            #pragma unroll
            for (int off = 16; off; off >>= 1) {
                #pragma unroll
                for (int u = 0; u < 4; ++u)
                    d[u] += __shfl_xor_sync(0xffffffff, d[u], off);
            }
            #pragma unroll
            for (int u = 0; u < 4; ++u) __stcs(&vd[(r0 + u) * EDV + t], bb4[u]);
            #pragma unroll
            for (int u = 0; u < 4; ++u) {
                float p = expf(d[u] * scale);
                lsum += p;
                cx += p * bb4[u].x;
                cy += p * bb4[u].y;
                cz += p * bb4[u].z;
                cw += p * bb4[u].w;
            }
        }
        // 2-row epilogue (30 % 4 == 38 % 4 == 2)
        {
            float4 a[2], bb4[2];
            #pragma unroll
            for (int u = 0; u < 2; ++u) a[u]   = __ldcs(&ks[(r0 + u) * EDV + t]);
            #pragma unroll
            for (int u = 0; u < 2; ++u) bb4[u] = __ldcs(&vs[(r0 + u) * EDV + t]);
            #pragma unroll
            for (int u = 0; u < 2; ++u) __stcs(&kd[(r0 + u) * EDV + t], a[u]);
            float d[2];
            #pragma unroll
            for (int u = 0; u < 2; ++u)
                d[u] = a[u].x * q.x + a[u].y * q.y + a[u].z * q.z + a[u].w * q.w;
            #pragma unroll
            for (int off = 16; off; off >>= 1) {
                #pragma unroll
                for (int u = 0; u < 2; ++u)
                    d[u] += __shfl_xor_sync(0xffffffff, d[u], off);
            }
            #pragma unroll
            for (int u = 0; u < 2; ++u) __stcs(&vd[(r0 + u) * EDV + t], bb4[u]);
            #pragma unroll
            for (int u = 0; u < 2; ++u) {
                float p = expf(d[u] * scale);
                lsum += p;
                cx += p * bb4[u].x;
                cy += p * bb4[u].y;
                cz += p * bb4[u].z;
                cw += p * bb4[u].w;
            }
        }
        if (lane == 0) atomicAdd(&g_hsum[h], lsum);
        int c = 4 * t;
        atomicAdd(&g_vals[c],     cx);
        atomicAdd(&g_vals[c + 1], cy);
        atomicAdd(&g_vals[c + 2], cz);
        atomicAdd(&g_vals[c + 3], cw);
    }

    // ---------------- barrier 2: all stream contributions in ----------------
    __threadfence();
    __syncthreads();
    if (t == 0) {
        atomicAdd(&g_scnt, 1u);
        unsigned target = (epoch + 1u) * 256u;
        while (*(volatile unsigned*)&g_scnt < target) __nanosleep(32);
    }
    __syncthreads();
    __threadfence();

    // ------------------------- phase 3: oproj -------------------------
    {
        // per-head tail weight (redundant per block, race-free)
        int lane = t & 31;
        int h = t >> 5;
        float4 qv = ((const float4*)g_q)[t];
        float4 kt = ((const float4*)k_tail)[t];
        float d = qv.x * kt.x + qv.y * kt.y + qv.z * kt.z + qv.w * kt.w;
        #pragma unroll
        for (int off = 16; off; off >>= 1)
            d += __shfl_xor_sync(0xffffffff, d, off);
        if (lane == 0) {
            float e = expf(d * scale);
            se[h] = e;
            ssinv[h] = 1.f / (g_hsum[h] + e);
        }
        __syncthreads();

        int bi = b >> 5, bj = b & 31;
        int i0 = bi * 256;
        if (t < 256) {
            int gi = i0 + t;
            int hh = gi >> 7;
            sxs[t] = (g_vals[gi] + se[hh] * v_tail[gi]) * ssinv[hh];
        }
        __syncthreads();

        int jq = t & 15;
        int isub = t >> 4;
        int jv = bj * 16 + jq;
        const float4* W4 = (const float4*)Wo;
        int rbase = isub * 8;

        float4 acc = make_float4(0.f, 0.f, 0.f, 0.f);
        #pragma unroll
        for (int r = 0; r < 8; ++r) {
            float s = sxs[rbase + r];
            float4 w = __ldcs(&W4[(size_t)(i0 + rbase + r) * EDV + jv]);
            acc.x += s * w.x; acc.y += s * w.y;
            acc.z += s * w.z; acc.w += s * w.w;
        }
        red4[isub][jq] = acc;
        __syncthreads();
        if (t < 16) {
            float4 s = red4[0][t];
            #pragma unroll
            for (int u = 1; u < 32; ++u) {
                s.x += red4[u][t].x; s.y += red4[u][t].y;
                s.z += red4[u][t].z; s.w += red4[u][t].w;
            }
            int j = bj * 64 + t * 4;
            atomicAdd(&out_i[j],     s.x);
            atomicAdd(&out_i[j + 1], s.y);
            atomicAdd(&out_i[j + 2], s.z);
            atomicAdd(&out_i[j + 3], s.w);
        }
    }
}

extern "C" void kernel_launch(void* const* d_in, const int* in_sizes, int n_in,
                              void* d_out, int out_size) {
    const float* x  = (const float*)d_in[0];
    const float* v  = (const float*)d_in[1];
    const float* k  = (const float*)d_in[2];
    const float* Wv = (const float*)d_in[3];
    const float* bv = (const float*)d_in[4];
    const float* Wq = (const float*)d_in[5];
    const float* bq = (const float*)d_in[6];
    const float* Wk = (const float*)d_in[7];
    const float* bk = (const float*)d_in[8];
    const float* Wo = (const float*)d_in[9];
    const float* bo = (const float*)d_in[10];

    float* out   = (float*)d_out;
    float* out_i = out;                               // [2048]
    float* out_v = out + ED;                          // [8193, 2048]
    float* out_k = out_v + (size_t)L1 * ED;           // [8193, 2048]
    float* k_tail = out_k + (size_t)LCACHE * ED;
    float* v_tail = out_v + (size_t)LCACHE * ED;
    const float scale = 0.08838834764831845f;

    mega_kernel<<<256, 512>>>(k, v, x, Wq, bq, Wk, bk, Wv, bv, Wo, bo,
                              out_k, out_v, k_tail, v_tail, out_i, scale);
}